// round 2
// baseline (speedup 1.0000x reference)
#include <cuda_runtime.h>
#include <mma.h>
#include <math.h>

using namespace nvcuda;

namespace {
constexpr int Bb = 128;
constexpr int Qq = 512;
constexpr int Tt = 512;
constexpr int Dd = 256;
constexpr int QT = 64;            // queries per CTA
constexpr int NW = 8;             // warps per CTA
constexpr int THREADS = NW * 32;  // 256
constexpr int QLD = 264;          // padded ld for Q tile (floats)
constexpr int KLD = 36;           // padded ld for K chunk (floats)
constexpr int VLD = 260;          // padded ld for V chunk (floats)
constexpr float SCALE = 0.0625f;  // 1/sqrt(256)

constexpr int S_ELEMS = QT * Tt;        // 32768 floats (scores / attended scratch)
constexpr int Q_ELEMS = QT * QLD;       // 16896 floats (Q tile; reused for V chunks)
constexpr int K_ELEMS = 64 * KLD;       // 2304 floats (K chunk)
constexpr int SMEM_FLOATS = S_ELEMS + Q_ELEMS + K_ELEMS + QT;  // + rowinv[64]
constexpr int SMEM_BYTES = SMEM_FLOATS * 4;                     // 208384 B
}  // namespace

using FragA  = wmma::fragment<wmma::matrix_a, 16, 16, 8, wmma::precision::tf32, wmma::row_major>;
using FragBc = wmma::fragment<wmma::matrix_b, 16, 16, 8, wmma::precision::tf32, wmma::col_major>;
using FragBr = wmma::fragment<wmma::matrix_b, 16, 16, 8, wmma::precision::tf32, wmma::row_major>;
using FragC  = wmma::fragment<wmma::accumulator, 16, 16, 8, float>;

__global__ void zero_out_kernel(float* out) {
    out[blockIdx.x * 256 + threadIdx.x] = 0.0f;
}

__global__ void __launch_bounds__(THREADS, 1)
attn_kernel(const float* __restrict__ inputs, const float* __restrict__ query,
            float* __restrict__ out) {
    extern __shared__ float sm[];
    float* S      = sm;                 // [QT][Tt] scores, later [QT][Dd] attended
    float* Qs     = S + S_ELEMS;        // [QT][QLD] Q tile, later V chunks
    float* Ks     = Qs + Q_ELEMS;       // [64][KLD] K chunk
    float* rowinv = Ks + K_ELEMS;       // [QT]

    const int tid   = threadIdx.x;
    const int wid   = tid >> 5;
    const int lane  = tid & 31;
    const int batch = blockIdx.x >> 3;        // 8 q-tiles per batch
    const int q0    = (blockIdx.x & 7) * QT;

    const float* Qg = query  + ((size_t)batch * Qq + q0) * Dd;
    const float* Kg = inputs + (size_t)batch * Tt * Dd;   // keys == values

    // ---- Load Q tile [QT][Dd] into SMEM (coalesced) ----
    for (int idx = tid; idx < QT * Dd; idx += THREADS) {
        int r = idx >> 8, c = idx & 255;
        Qs[r * QLD + c] = Qg[r * Dd + c];
    }

    // ---- Phase 1: S[64,512] = scale * Q . K^T  (TF32 mma) ----
    const int wq = wid & 3;   // warp row tile (16 q-rows each, 4 tiles)
    const int wt = wid >> 2;  // warp col tile (32 t-cols each, 2 tiles)

    for (int tt = 0; tt < Tt / 64; ++tt) {
        FragC c0, c1;
        wmma::fill_fragment(c0, 0.0f);
        wmma::fill_fragment(c1, 0.0f);

        for (int dc = 0; dc < Dd / 32; ++dc) {
            __syncthreads();  // protect Ks reuse (and Qs staging on first iter)
            // stage K chunk: rows t in [tt*64, tt*64+64), cols d in [dc*32, dc*32+32)
            for (int idx = tid; idx < 64 * 32; idx += THREADS) {
                int t = idx >> 5, c = idx & 31;
                Ks[t * KLD + c] = Kg[(size_t)(tt * 64 + t) * Dd + dc * 32 + c];
            }
            __syncthreads();

#pragma unroll
            for (int ks = 0; ks < 4; ++ks) {
                FragA a;
                wmma::load_matrix_sync(a, Qs + wq * 16 * QLD + dc * 32 + ks * 8, QLD);
#pragma unroll
                for (int i = 0; i < a.num_elements; ++i)
                    a.x[i] = wmma::__float_to_tf32(a.x[i]);

                FragBc b0, b1;
                // B[d][t] = K[t][d]  (col-major view of Ks, ldm = KLD)
                wmma::load_matrix_sync(b0, Ks + (wt * 32 +  0) * KLD + ks * 8, KLD);
                wmma::load_matrix_sync(b1, Ks + (wt * 32 + 16) * KLD + ks * 8, KLD);
#pragma unroll
                for (int i = 0; i < b0.num_elements; ++i) {
                    b0.x[i] = wmma::__float_to_tf32(b0.x[i]);
                    b1.x[i] = wmma::__float_to_tf32(b1.x[i]);
                }
                wmma::mma_sync(c0, a, b0, c0);
                wmma::mma_sync(c1, a, b1, c1);
            }
        }
#pragma unroll
        for (int i = 0; i < c0.num_elements; ++i) {
            c0.x[i] *= SCALE;
            c1.x[i] *= SCALE;
        }
        wmma::store_matrix_sync(S + (wq * 16) * Tt + tt * 64 + wt * 32,      c0, Tt, wmma::mem_row_major);
        wmma::store_matrix_sync(S + (wq * 16) * Tt + tt * 64 + wt * 32 + 16, c1, Tt, wmma::mem_row_major);
    }
    __syncthreads();

    // ---- Phase 2: softmax over T (in-place; normalization deferred) ----
    for (int r = wid * 8; r < wid * 8 + 8; ++r) {
        float* row = S + r * Tt;
        float m = -1e30f;
        for (int j = lane; j < Tt; j += 32) m = fmaxf(m, row[j]);
#pragma unroll
        for (int o = 16; o > 0; o >>= 1) m = fmaxf(m, __shfl_xor_sync(0xffffffffu, m, o));
        float s = 0.0f;
        for (int j = lane; j < Tt; j += 32) {
            float e = __expf(row[j] - m);
            row[j] = e;
            s += e;
        }
#pragma unroll
        for (int o = 16; o > 0; o >>= 1) s += __shfl_xor_sync(0xffffffffu, s, o);
        if (lane == 0) rowinv[r] = 1.0f / s;
    }
    __syncthreads();

    // ---- Phase 3: attended[64,256] = P[64,512] . V[512,256] (TF32 mma) ----
    const int wd = wt;    // warp col tile: 128 d-cols each
    float* Vs = Qs;       // reuse Q-tile region for V chunks
    FragC acc[8];
#pragma unroll
    for (int f = 0; f < 8; ++f) wmma::fill_fragment(acc[f], 0.0f);

    for (int tc = 0; tc < Tt / 16; ++tc) {
        __syncthreads();  // protect Vs reuse
        // stage V chunk: rows t in [tc*16, tc*16+16), all 256 cols
        for (int idx = tid; idx < 16 * Dd; idx += THREADS) {
            int r = idx >> 8, c = idx & 255;
            Vs[r * VLD + c] = Kg[(size_t)(tc * 16 + r) * Dd + c];
        }
        __syncthreads();

#pragma unroll
        for (int ks = 0; ks < 2; ++ks) {
            FragA a;
            wmma::load_matrix_sync(a, S + wq * 16 * Tt + tc * 16 + ks * 8, Tt);
#pragma unroll
            for (int i = 0; i < a.num_elements; ++i)
                a.x[i] = wmma::__float_to_tf32(a.x[i]);
#pragma unroll
            for (int f = 0; f < 8; ++f) {
                FragBr b;
                wmma::load_matrix_sync(b, Vs + (ks * 8) * VLD + wd * 128 + f * 16, VLD);
#pragma unroll
                for (int i = 0; i < b.num_elements; ++i)
                    b.x[i] = wmma::__float_to_tf32(b.x[i]);
                wmma::mma_sync(acc[f], a, b, acc[f]);
            }
        }
    }
    __syncthreads();  // all warps done reading P before we overwrite S

    // store attended (pre-normalization) into S as [QT][Dd]
#pragma unroll
    for (int f = 0; f < 8; ++f)
        wmma::store_matrix_sync(S + (wq * 16) * Dd + wd * 128 + f * 16, acc[f], Dd,
                                wmma::mem_row_major);
    __syncthreads();

    // ---- Phase 4: pool over q (with deferred softmax normalization) ----
    float sum = 0.0f;
    for (int r = 0; r < QT; ++r)
        sum += S[r * Dd + tid] * rowinv[r];   // conflict-free: consecutive tid -> consecutive addr
    atomicAdd(out + batch * Dd + tid, sum);
}

extern "C" void kernel_launch(void* const* d_in, const int* in_sizes, int n_in,
                              void* d_out, int out_size) {
    const float* inputs = (const float*)d_in[0];  // [B, T, D]
    const float* query  = (const float*)d_in[1];  // [B, Q, D]
    float* out = (float*)d_out;                   // [B, D]

    cudaFuncSetAttribute(attn_kernel, cudaFuncAttributeMaxDynamicSharedMemorySize,
                         SMEM_BYTES);

    zero_out_kernel<<<(Bb * Dd) / 256, 256>>>(out);
    attn_kernel<<<Bb * (Qq / QT), THREADS, SMEM_BYTES>>>(inputs, query, out);
}

// round 3
// speedup vs baseline: 2.2443x; 2.2443x over previous
#include <cuda_runtime.h>
#include <mma.h>
#include <math.h>

using namespace nvcuda;

namespace {
constexpr int Bb = 128;
constexpr int Qq = 512;
constexpr int Tt = 512;
constexpr int Dd = 256;
constexpr int QT = 32;            // queries per CTA
constexpr int NW = 8;
constexpr int THREADS = NW * 32;  // 256
constexpr int QLD = 260;          // padded ld for Q tile (mult of 4)
constexpr int KLD = 20;           // padded ld for K chunk (mult of 4)
constexpr int TTILE = 128;        // t-cols per outer tile
constexpr int DCH = 16;           // d-cols per K stage
constexpr float SCALE = 0.0625f;  // 1/sqrt(256)

constexpr int S_ELEMS = QT * Tt;          // 16384 floats (64 KB)
constexpr int Q_ELEMS = QT * QLD;         // 8320 floats (33.3 KB)
constexpr int K_ELEMS = TTILE * KLD;      // 2560 floats (10.2 KB)
constexpr int SMEM_FLOATS = S_ELEMS + Q_ELEMS + K_ELEMS + QT;
constexpr int SMEM_BYTES = SMEM_FLOATS * 4;   // ~110 KB -> 2 CTAs/SM
}  // namespace

__device__ float g_colsum[Bb * Tt];   // per-batch weight column sums (256 KB scratch)

using FragA  = wmma::fragment<wmma::matrix_a, 16, 16, 8, wmma::precision::tf32, wmma::row_major>;
using FragBc = wmma::fragment<wmma::matrix_b, 16, 16, 8, wmma::precision::tf32, wmma::col_major>;
using FragC  = wmma::fragment<wmma::accumulator, 16, 16, 8, float>;

__device__ __forceinline__ float to_tf32(float x) {
    float y;
    asm("cvt.rna.tf32.f32 %0, %1;" : "=f"(y) : "f"(x));
    return y;
}

__global__ void zero_colsum_kernel() {
    g_colsum[blockIdx.x * 256 + threadIdx.x] = 0.0f;
}

// Kernel A: per (batch, 32-query tile): S = scale*Q.K^T, softmax rows,
// column-sum with deferred 1/rowsum normalization -> atomicAdd into g_colsum.
__global__ void __launch_bounds__(THREADS, 2)
attn_scores_kernel(const float* __restrict__ inputs, const float* __restrict__ query) {
    extern __shared__ float sm[];
    float* S      = sm;                 // [QT][Tt]
    float* Qs     = S + S_ELEMS;        // [QT][QLD] (tf32-rounded)
    float* Ks     = Qs + Q_ELEMS;       // [TTILE][KLD] (tf32-rounded)
    float* rowinv = Ks + K_ELEMS;       // [QT]

    const int tid   = threadIdx.x;
    const int wid   = tid >> 5;
    const int lane  = tid & 31;
    const int batch = blockIdx.x >> 4;         // 16 q-tiles per batch
    const int q0    = (blockIdx.x & 15) * QT;

    const float* Qg = query  + ((size_t)batch * Qq + q0) * Dd;
    const float* Kg = inputs + (size_t)batch * Tt * Dd;

    // Load + tf32-round Q tile [QT][Dd] (coalesced)
    for (int idx = tid; idx < QT * Dd; idx += THREADS) {
        int r = idx >> 8, c = idx & 255;
        Qs[r * QLD + c] = to_tf32(Qg[r * Dd + c]);
    }

    // ---- Phase 1: S[32,512] = scale * Q . K^T (tf32 mma) ----
    const int wq = wid & 1;   // 16-row tile
    const int wt = wid >> 1;  // 32-col tile within TTILE

    for (int tt = 0; tt < Tt / TTILE; ++tt) {
        FragC c0, c1;
        wmma::fill_fragment(c0, 0.0f);
        wmma::fill_fragment(c1, 0.0f);

        for (int dc = 0; dc < Dd / DCH; ++dc) {
            __syncthreads();
            // stage K chunk: rows t in [tt*128, +128), cols d in [dc*16, +16)
            for (int idx = tid; idx < TTILE * DCH; idx += THREADS) {
                int t = idx >> 4, c = idx & 15;
                Ks[t * KLD + c] =
                    to_tf32(Kg[(size_t)(tt * TTILE + t) * Dd + dc * DCH + c]);
            }
            __syncthreads();

#pragma unroll
            for (int ks = 0; ks < DCH / 8; ++ks) {
                FragA a;
                wmma::load_matrix_sync(a, Qs + wq * 16 * QLD + dc * DCH + ks * 8, QLD);
                FragBc b0, b1;
                wmma::load_matrix_sync(b0, Ks + (wt * 32 +  0) * KLD + ks * 8, KLD);
                wmma::load_matrix_sync(b1, Ks + (wt * 32 + 16) * KLD + ks * 8, KLD);
                wmma::mma_sync(c0, a, b0, c0);
                wmma::mma_sync(c1, a, b1, c1);
            }
        }
#pragma unroll
        for (int i = 0; i < c0.num_elements; ++i) {
            c0.x[i] *= SCALE;
            c1.x[i] *= SCALE;
        }
        wmma::store_matrix_sync(S + (wq * 16) * Tt + tt * TTILE + wt * 32,      c0, Tt, wmma::mem_row_major);
        wmma::store_matrix_sync(S + (wq * 16) * Tt + tt * TTILE + wt * 32 + 16, c1, Tt, wmma::mem_row_major);
    }
    __syncthreads();

    // ---- Phase 2: row softmax (normalization deferred) ----
    for (int r = wid * 4; r < wid * 4 + 4; ++r) {
        float* row = S + r * Tt;
        float m = -1e30f;
        for (int j = lane; j < Tt; j += 32) m = fmaxf(m, row[j]);
#pragma unroll
        for (int o = 16; o > 0; o >>= 1) m = fmaxf(m, __shfl_xor_sync(0xffffffffu, m, o));
        float s = 0.0f;
        for (int j = lane; j < Tt; j += 32) {
            float e = __expf(row[j] - m);
            row[j] = e;
            s += e;
        }
#pragma unroll
        for (int o = 16; o > 0; o >>= 1) s += __shfl_xor_sync(0xffffffffu, s, o);
        if (lane == 0) rowinv[r] = 1.0f / s;
    }
    __syncthreads();

    // ---- Phase 3: weight column sums -> global accumulation ----
    // each thread handles 2 t-columns; reads down a column are conflict-free
#pragma unroll
    for (int h = 0; h < 2; ++h) {
        int t = tid + h * THREADS;
        float sum = 0.0f;
#pragma unroll 8
        for (int r = 0; r < QT; ++r) sum += S[r * Tt + t] * rowinv[r];
        atomicAdd(&g_colsum[batch * Tt + t], sum);
    }
}

// Kernel B: out[b,d] = sum_t c[b,t] * V[t,d]   (memory-bound matvec)
__global__ void __launch_bounds__(256)
pool_kernel(const float* __restrict__ inputs, float* __restrict__ out) {
    __shared__ float c[Tt];
    const int b = blockIdx.x;
    const int d = threadIdx.x;
    for (int t = threadIdx.x; t < Tt; t += 256) c[t] = g_colsum[b * Tt + t];
    __syncthreads();

    const float* V = inputs + (size_t)b * Tt * Dd;
    float a0 = 0.0f, a1 = 0.0f, a2 = 0.0f, a3 = 0.0f;
#pragma unroll 4
    for (int t = 0; t < Tt; t += 4) {
        a0 += c[t + 0] * V[(size_t)(t + 0) * Dd + d];
        a1 += c[t + 1] * V[(size_t)(t + 1) * Dd + d];
        a2 += c[t + 2] * V[(size_t)(t + 2) * Dd + d];
        a3 += c[t + 3] * V[(size_t)(t + 3) * Dd + d];
    }
    out[b * Dd + d] = (a0 + a1) + (a2 + a3);
}

extern "C" void kernel_launch(void* const* d_in, const int* in_sizes, int n_in,
                              void* d_out, int out_size) {
    const float* inputs = (const float*)d_in[0];  // [B, T, D]
    const float* query  = (const float*)d_in[1];  // [B, Q, D]
    float* out = (float*)d_out;                   // [B, D]

    cudaFuncSetAttribute(attn_scores_kernel,
                         cudaFuncAttributeMaxDynamicSharedMemorySize, SMEM_BYTES);

    zero_colsum_kernel<<<(Bb * Tt) / 256, 256>>>();
    attn_scores_kernel<<<Bb * (Qq / QT), THREADS, SMEM_BYTES>>>(inputs, query);
    pool_kernel<<<Bb, 256>>>(inputs, out);
}

// round 10
// speedup vs baseline: 4.2239x; 1.8821x over previous
#include <cuda_runtime.h>
#include <cuda_fp16.h>
#include <mma.h>
#include <cstdint>
#include <math.h>

using namespace nvcuda;

namespace {
constexpr int Bb = 128;
constexpr int Qq = 512;
constexpr int Tt = 512;
constexpr int Dd = 256;
constexpr int QT = 32;            // queries per CTA
constexpr int THREADS = 256;      // 8 warps
constexpr int TTILE = 256;        // t-cols per pass (warp wt owns 32 cols)
constexpr int DCH = 16;           // d-cols per K stage
constexpr int NSTAGE = 32;        // 2 passes x 16 d-chunks
constexpr int QLD = 260;          // Q smem ld (mult of 4 for wmma)
constexpr int KLD = 20;           // K smem ld (mult of 4, 8B-aligned rows)
constexpr int SLD = 514;          // S (fp16) ld — odd stride/2: conflict-free col reads
constexpr int SCRLD = 20;         // epilogue scratch ld (mult of 4)
constexpr int SCR_WARP_BYTES = QT * SCRLD * 4;  // 2560 B per-warp scratch
constexpr float SCALE = 0.0625f;  // 1/sqrt(256)

constexpr int KBUF   = 256 * KLD * 4;        // 20480 B per K buffer
constexpr int SM_Q   = 0;                    // 32*260*4 = 33280
constexpr int SM_K   = SM_Q + QT * QLD * 4;  // 2 bufs -> 40960
constexpr int SM_S   = SM_K + 2 * KBUF;      // 32*514*2 = 32896
constexpr int SM_ROW = SM_S + QT * SLD * 2;
constexpr int SM_RINV = SM_ROW + 128;
constexpr int SMEM_BYTES = SM_RINV + 128;    // ~107.5 KB -> 2 CTAs/SM

static_assert(8 * SCR_WARP_BYTES <= KBUF, "scratch must fit in K buffer 1");
}  // namespace

__device__ float g_colsum[Bb * Tt];

using FragA = wmma::fragment<wmma::matrix_a, 16, 16, 8, wmma::precision::tf32, wmma::row_major>;
using FragB = wmma::fragment<wmma::matrix_b, 16, 16, 8, wmma::precision::tf32, wmma::col_major>;
using FragC = wmma::fragment<wmma::accumulator, 16, 16, 8, float>;

__device__ __forceinline__ uint32_t smem_u32(const void* p) {
    uint32_t a;
    asm("{ .reg .u64 t; cvta.to.shared.u64 t, %1; cvt.u32.u64 %0, t; }" : "=r"(a) : "l"(p));
    return a;
}
__device__ __forceinline__ float to_tf32(float x) {
    float y;
    asm("cvt.rna.tf32.f32 %0, %1;" : "=f"(y) : "f"(x));
    return y;
}

// Zeroes g_colsum and out each replay.
__global__ void zero_kernel(float* out) {
    int i = blockIdx.x * 256 + threadIdx.x;
    if (i < Bb * Tt) g_colsum[i] = 0.0f;
    if (i < Bb * Dd) out[i] = 0.0f;
}

// cp.async staging of one K chunk: 256 t-rows x 16 d-cols (raw fp32; HMMA.TF32
// truncates operand mantissas in hardware). 8B copies, 8 per thread.
__device__ __forceinline__ void issue_stage(uint32_t sb, const float* __restrict__ Kg,
                                            int stage, int tid) {
    const int buf = stage & 1, p = stage >> 4, dc = stage & 15;
    const float* base = Kg + (size_t)p * TTILE * Dd + dc * DCH;
    const uint32_t dbase = sb + SM_K + buf * KBUF;
#pragma unroll
    for (int it = 0; it < 8; ++it) {
        int c = tid + it * THREADS;  // 0..2047
        int row = c >> 3, q = c & 7;
        uint32_t dst = dbase + (uint32_t)(row * KLD + q * 2) * 4;
        const float* g = base + (size_t)row * Dd + q * 2;
        asm volatile("cp.async.ca.shared.global [%0], [%1], 8;" :: "r"(dst), "l"(g));
    }
    asm volatile("cp.async.commit_group;" ::: "memory");
}

// Per CTA: (batch, 32-query tile). S = softmax(scale*Q.K^T) rows; accumulate
// weight column sums into g_colsum.
__global__ void __launch_bounds__(THREADS, 2)
score_kernel(const float* __restrict__ inputs, const float* __restrict__ query) {
    extern __shared__ char smem[];
    const uint32_t sb = smem_u32(smem);
    const int tid = threadIdx.x, wid = tid >> 5, lane = tid & 31;
    const int batch = blockIdx.x >> 4;
    const int q0 = (blockIdx.x & 15) * QT;

    const float* Qg = query + ((size_t)batch * Qq + q0) * Dd;
    const float* Kg = inputs + (size_t)batch * Tt * Dd;

    float* Qs = (float*)(smem + SM_Q);
    float* rowsum = (float*)(smem + SM_ROW);
    float* rinv = (float*)(smem + SM_RINV);
    __half* Sh = (__half*)(smem + SM_S);

    issue_stage(sb, Kg, 0, tid);  // start K copies ASAP

    if (tid < QT) rowsum[tid] = 0.0f;

    // Stage Q (scale folded, tf32-rounded)
#pragma unroll
    for (int it = 0; it < 8; ++it) {
        int i = tid + it * THREADS;  // float4 index, 0..2047
        int r = i >> 6, c4 = i & 63;
        float4 v = ((const float4*)Qg)[r * 64 + c4];
        float* q = Qs + r * QLD + c4 * 4;
        q[0] = to_tf32(v.x * SCALE);
        q[1] = to_tf32(v.y * SCALE);
        q[2] = to_tf32(v.z * SCALE);
        q[3] = to_tf32(v.w * SCALE);
    }

    FragC c00, c01, c10, c11;
    const int wt = wid;  // warp owns t-cols [wt*32, wt*32+32) within pass

    for (int stage = 0; stage < NSTAGE; ++stage) {
        const int buf = stage & 1, p = stage >> 4, dc = stage & 15;
        asm volatile("cp.async.wait_group 0;" ::: "memory");
        __syncthreads();
        if (stage + 1 < NSTAGE) issue_stage(sb, Kg, stage + 1, tid);

        if (dc == 0) {
            wmma::fill_fragment(c00, 0.0f);
            wmma::fill_fragment(c01, 0.0f);
            wmma::fill_fragment(c10, 0.0f);
            wmma::fill_fragment(c11, 0.0f);
        }
        const float* Kb = (const float*)(smem + SM_K + buf * KBUF);
#pragma unroll
        for (int ks = 0; ks < 2; ++ks) {
            FragA a0, a1;
            FragB b0, b1;
            wmma::load_matrix_sync(a0, Qs + dc * DCH + ks * 8, QLD);
            wmma::load_matrix_sync(a1, Qs + 16 * QLD + dc * DCH + ks * 8, QLD);
            wmma::load_matrix_sync(b0, Kb + (wt * 32 + 0) * KLD + ks * 8, KLD);
            wmma::load_matrix_sync(b1, Kb + (wt * 32 + 16) * KLD + ks * 8, KLD);
            wmma::mma_sync(c00, a0, b0, c00);
            wmma::mma_sync(c01, a0, b1, c01);
            wmma::mma_sync(c10, a1, b0, c10);
            wmma::mma_sync(c11, a1, b1, c11);
        }

        if (dc == 15) {
            // End of pass p: exp + fp16 store + rowsum partials.
            __syncthreads();  // quiesce buf1 readers; scratch lives there
            // per-warp scratch [32][20] fp32 = 2560 B; 8 warps fill buf1 exactly
            float* scr = (float*)(smem + SM_K + KBUF + wid * SCR_WARP_BYTES);
            float rs = 0.0f;
            const int tbase = p * TTILE + wt * 32;
#pragma unroll
            for (int h = 0; h < 2; ++h) {
                wmma::store_matrix_sync(scr, h ? c01 : c00, SCRLD, wmma::mem_row_major);
                wmma::store_matrix_sync(scr + 16 * SCRLD, h ? c11 : c10, SCRLD,
                                        wmma::mem_row_major);
                __syncwarp();
                const int r = lane;
#pragma unroll
                for (int c = 0; c < 16; ++c) {
                    float e = __expf(scr[r * SCRLD + c]);
                    rs += e;
                    Sh[r * SLD + tbase + h * 16 + c] = __float2half_rn(e);
                }
                __syncwarp();
            }
            atomicAdd(&rowsum[lane], rs);
        }
    }
    __syncthreads();
    if (tid < QT) rinv[tid] = 1.0f / rowsum[tid];
    __syncthreads();

    // Column sums of normalized weights -> global
#pragma unroll
    for (int h = 0; h < 2; ++h) {
        int t = tid + h * THREADS;
        float s = 0.0f;
#pragma unroll 8
        for (int r = 0; r < QT; ++r) s += __half2float(Sh[r * SLD + t]) * rinv[r];
        atomicAdd(&g_colsum[batch * Tt + t], s);
    }
}

// out[b,d] += sum_{t in slice} colsum[b,t] * V[t,d]; 4 t-slices per batch.
__global__ void __launch_bounds__(256)
pool_kernel(const float* __restrict__ inputs, float* __restrict__ out) {
    __shared__ float c[128];
    const int b = blockIdx.x >> 2;
    const int t0 = (blockIdx.x & 3) * 128;
    if (threadIdx.x < 128) c[threadIdx.x] = g_colsum[b * Tt + t0 + threadIdx.x];
    __syncthreads();

    const float* V = inputs + ((size_t)b * Tt + t0) * Dd;
    const int d = threadIdx.x;
    float a0 = 0.0f, a1 = 0.0f, a2 = 0.0f, a3 = 0.0f;
#pragma unroll 4
    for (int t = 0; t < 128; t += 4) {
        a0 += c[t + 0] * V[(size_t)(t + 0) * Dd + d];
        a1 += c[t + 1] * V[(size_t)(t + 1) * Dd + d];
        a2 += c[t + 2] * V[(size_t)(t + 2) * Dd + d];
        a3 += c[t + 3] * V[(size_t)(t + 3) * Dd + d];
    }
    atomicAdd(&out[b * Dd + d], (a0 + a1) + (a2 + a3));
}

extern "C" void kernel_launch(void* const* d_in, const int* in_sizes, int n_in,
                              void* d_out, int out_size) {
    const float* inputs = (const float*)d_in[0];  // [B, T, D]
    const float* query  = (const float*)d_in[1];  // [B, Q, D]
    float* out = (float*)d_out;                   // [B, D]

    cudaFuncSetAttribute(score_kernel,
                         cudaFuncAttributeMaxDynamicSharedMemorySize, SMEM_BYTES);

    zero_kernel<<<256, 256>>>(out);
    score_kernel<<<Bb * (Qq / QT), THREADS, SMEM_BYTES>>>(inputs, query);
    pool_kernel<<<Bb * 4, 256>>>(inputs, out);
}

// round 11
// speedup vs baseline: 5.8833x; 1.3929x over previous
#include <cuda_runtime.h>
#include <cuda_fp16.h>
#include <cstdint>
#include <math.h>

namespace {
constexpr int Bb = 128;
constexpr int Qq = 512;
constexpr int Tt = 512;
constexpr int Dd = 256;
constexpr int QT = 64;            // queries per CTA
constexpr int THREADS = 512;      // 16 warps
constexpr int TTILE = 256;        // t-cols per pass; warp owns 32
constexpr int DCH = 16;           // d-cols per K stage
constexpr int NSTAGE = 32;        // 2 passes x 16 d-chunks
constexpr int QLD = 260;          // Q smem ld (1040B rows -> 16B rotation, conflict-free)
constexpr int KLD = 20;           // K smem ld (80B rows, conflict-free)
constexpr int SLD = 520;          // S fp16 ld (1040B rows -> 16B rotation for half2 stores)
constexpr float SCALE = 0.0625f;  // 1/sqrt(256)

constexpr int KBUF    = 256 * KLD * 4;         // 20480 B per K buffer
constexpr int SM_Q    = 0;                     // 64*260*4 = 66560
constexpr int SM_K    = SM_Q + QT * QLD * 4;   // 2 bufs -> 40960
constexpr int SM_S    = SM_K + 2 * KBUF;       // 64*520*2 = 66560
constexpr int SM_ROW  = SM_S + QT * SLD * 2;
constexpr int SM_RINV = SM_ROW + 256;
constexpr int SMEM_BYTES = SM_RINV + 256;      // 174848 B -> 1 CTA/SM
}  // namespace

__device__ float g_partial[Bb * 8 * Tt];  // per-(batch,qtile) colsum partials (2 MB)

__device__ __forceinline__ uint32_t smem_u32(const void* p) {
    uint32_t a;
    asm("{ .reg .u64 t; cvta.to.shared.u64 t, %1; cvt.u32.u64 %0, t; }" : "=r"(a) : "l"(p));
    return a;
}
__device__ __forceinline__ float to_tf32(float x) {
    float y;
    asm("cvt.rna.tf32.f32 %0, %1;" : "=f"(y) : "f"(x));
    return y;
}
// D += A.B with architecturally-specified fragment layouts (PTX m16n8k8 tf32):
// A: a0(g,tg) a1(g+8,tg) a2(g,tg+4) a3(g+8,tg+4);  B: b0(k=tg,n=g) b1(k=tg+4,n=g)
// C: c0(g,2tg) c1(g,2tg+1) c2(g+8,2tg) c3(g+8,2tg+1)   [g=lane>>2, tg=lane&3]
__device__ __forceinline__ void mma_tf32(float* c, const uint32_t* a, uint32_t b0,
                                         uint32_t b1) {
    asm volatile(
        "mma.sync.aligned.m16n8k8.row.col.f32.tf32.tf32.f32 "
        "{%0,%1,%2,%3}, {%4,%5,%6,%7}, {%8,%9}, {%0,%1,%2,%3};"
        : "+f"(c[0]), "+f"(c[1]), "+f"(c[2]), "+f"(c[3])
        : "r"(a[0]), "r"(a[1]), "r"(a[2]), "r"(a[3]), "r"(b0), "r"(b1));
}

// cp.async one K chunk: 256 t-rows x 16 d-cols (raw fp32; HMMA truncates to tf32).
__device__ __forceinline__ void issue_stage(uint32_t sb, const float* __restrict__ Kg,
                                            int stage, int tid) {
    const int buf = stage & 1, p = stage >> 4, dc = stage & 15;
    const float* base = Kg + (size_t)p * TTILE * Dd + dc * DCH;
    const uint32_t dbase = sb + SM_K + buf * KBUF;
#pragma unroll
    for (int it = 0; it < 4; ++it) {
        int c = tid + it * THREADS;  // 0..2047
        int row = c >> 3, q = c & 7;
        uint32_t dst = dbase + (uint32_t)(row * KLD + q * 2) * 4;
        const float* g = base + (size_t)row * Dd + q * 2;
        asm volatile("cp.async.ca.shared.global [%0], [%1], 8;" :: "r"(dst), "l"(g));
    }
    asm volatile("cp.async.commit_group;" ::: "memory");
}

// Per CTA: (batch, 64-query tile). S = softmax rows of scale*Q.K^T; write
// weight column-sum partial to g_partial (no atomics).
__global__ void __launch_bounds__(THREADS, 1)
score_kernel(const float* __restrict__ inputs, const float* __restrict__ query) {
    extern __shared__ char smem[];
    const uint32_t sb = smem_u32(smem);
    const int tid = threadIdx.x, wid = tid >> 5, lane = tid & 31;
    const int wq = wid >> 3;   // q-half (32 rows)
    const int wt = wid & 7;    // 32 t-cols within pass
    const int g = lane >> 2, tg = lane & 3;
    const int batch = blockIdx.x >> 3;
    const int q0 = (blockIdx.x & 7) * QT;

    const float* Qg = query + ((size_t)batch * Qq + q0) * Dd;
    const float* Kg = inputs + (size_t)batch * Tt * Dd;

    float* Qs = (float*)(smem + SM_Q);
    float* rowsum = (float*)(smem + SM_ROW);
    float* rinv = (float*)(smem + SM_RINV);
    __half* Sh = (__half*)(smem + SM_S);

    issue_stage(sb, Kg, 0, tid);  // start K copies ASAP

    if (tid < QT) rowsum[tid] = 0.0f;

    // Stage Q (scale folded, tf32-rounded), 64x256 -> 4096 float4
#pragma unroll
    for (int it = 0; it < 8; ++it) {
        int i = tid + it * THREADS;
        int r = i >> 6, c4 = i & 63;
        float4 v = ((const float4*)Qg)[r * 64 + c4];
        float* q = Qs + r * QLD + c4 * 4;
        q[0] = to_tf32(v.x * SCALE);
        q[1] = to_tf32(v.y * SCALE);
        q[2] = to_tf32(v.z * SCALE);
        q[3] = to_tf32(v.w * SCALE);
    }

    float acc[2][4][4];  // [mi][ni][c]

    for (int stage = 0; stage < NSTAGE; ++stage) {
        const int buf = stage & 1, p = stage >> 4, dc = stage & 15;
        asm volatile("cp.async.wait_group 0;" ::: "memory");
        __syncthreads();
        if (stage + 1 < NSTAGE) issue_stage(sb, Kg, stage + 1, tid);

        if (dc == 0) {
#pragma unroll
            for (int mi = 0; mi < 2; ++mi)
#pragma unroll
                for (int ni = 0; ni < 4; ++ni)
#pragma unroll
                    for (int c = 0; c < 4; ++c) acc[mi][ni][c] = 0.0f;
        }
        const float* Kb = (const float*)(smem + SM_K + buf * KBUF);

#pragma unroll
        for (int ks = 0; ks < 2; ++ks) {
            const int col = dc * DCH + ks * 8 + tg;
            uint32_t a[2][4];
#pragma unroll
            for (int mi = 0; mi < 2; ++mi) {
                const uint32_t* Ar =
                    (const uint32_t*)(Qs + (wq * 32 + mi * 16 + g) * QLD + col);
                a[mi][0] = Ar[0];
                a[mi][1] = Ar[8 * QLD];
                a[mi][2] = Ar[4];
                a[mi][3] = Ar[8 * QLD + 4];
            }
#pragma unroll
            for (int ni = 0; ni < 4; ++ni) {
                const uint32_t* Br =
                    (const uint32_t*)(Kb + (wt * 32 + ni * 8 + g) * KLD + ks * 8 + tg);
                uint32_t b0 = Br[0], b1 = Br[4];
                mma_tf32(acc[0][ni], a[0], b0, b1);
                mma_tf32(acc[1][ni], a[1], b0, b1);
            }
        }

        if (dc == 15) {
            // Register-direct epilogue for pass p: exp -> S (fp16), rowsum partials.
            float rsum[4] = {0.0f, 0.0f, 0.0f, 0.0f};
            const int tb = p * TTILE + wt * 32;
#pragma unroll
            for (int mi = 0; mi < 2; ++mi) {
                const int r = wq * 32 + mi * 16 + g;
#pragma unroll
                for (int ni = 0; ni < 4; ++ni) {
                    float e0 = __expf(acc[mi][ni][0]);
                    float e1 = __expf(acc[mi][ni][1]);
                    float e2 = __expf(acc[mi][ni][2]);
                    float e3 = __expf(acc[mi][ni][3]);
                    rsum[mi * 2 + 0] += e0 + e1;
                    rsum[mi * 2 + 1] += e2 + e3;
                    const int c = tb + ni * 8 + tg * 2;
                    *(__half2*)(Sh + r * SLD + c) = __floats2half2_rn(e0, e1);
                    *(__half2*)(Sh + (r + 8) * SLD + c) = __floats2half2_rn(e2, e3);
                }
            }
#pragma unroll
            for (int j = 0; j < 4; ++j) {
                rsum[j] += __shfl_xor_sync(0xffffffffu, rsum[j], 1);
                rsum[j] += __shfl_xor_sync(0xffffffffu, rsum[j], 2);
            }
            if (tg == 0) {
                atomicAdd(&rowsum[wq * 32 + g], rsum[0]);
                atomicAdd(&rowsum[wq * 32 + g + 8], rsum[1]);
                atomicAdd(&rowsum[wq * 32 + 16 + g], rsum[2]);
                atomicAdd(&rowsum[wq * 32 + 24 + g], rsum[3]);
            }
        }
    }
    __syncthreads();
    if (tid < QT) rinv[tid] = 1.0f / rowsum[tid];
    __syncthreads();

    // Column sums of normalized weights -> g_partial (one t per thread)
    const int t = tid;
    float s = 0.0f;
#pragma unroll 8
    for (int r = 0; r < QT; ++r) s += __half2float(Sh[r * SLD + t]) * rinv[r];
    g_partial[(size_t)blockIdx.x * Tt + t] = s;
}

// out[b,d] = sum_t (sum_j partial[b,j,t]) * V[t,d]
__global__ void __launch_bounds__(256)
pool_kernel(const float* __restrict__ inputs, float* __restrict__ out) {
    __shared__ float c[Tt];
    const int b = blockIdx.x;
    for (int t = threadIdx.x; t < Tt; t += 256) {
        float s = 0.0f;
#pragma unroll
        for (int j = 0; j < 8; ++j) s += g_partial[((size_t)b * 8 + j) * Tt + t];
        c[t] = s;
    }
    __syncthreads();

    const float* V = inputs + (size_t)b * Tt * Dd;
    const int d = threadIdx.x;
    float a0 = 0.0f, a1 = 0.0f, a2 = 0.0f, a3 = 0.0f;
#pragma unroll 4
    for (int t = 0; t < Tt; t += 4) {
        a0 += c[t + 0] * V[(size_t)(t + 0) * Dd + d];
        a1 += c[t + 1] * V[(size_t)(t + 1) * Dd + d];
        a2 += c[t + 2] * V[(size_t)(t + 2) * Dd + d];
        a3 += c[t + 3] * V[(size_t)(t + 3) * Dd + d];
    }
    out[b * Dd + d] = (a0 + a1) + (a2 + a3);
}

extern "C" void kernel_launch(void* const* d_in, const int* in_sizes, int n_in,
                              void* d_out, int out_size) {
    const float* inputs = (const float*)d_in[0];  // [B, T, D]
    const float* query  = (const float*)d_in[1];  // [B, Q, D]
    float* out = (float*)d_out;                   // [B, D]

    cudaFuncSetAttribute(score_kernel,
                         cudaFuncAttributeMaxDynamicSharedMemorySize, SMEM_BYTES);

    score_kernel<<<Bb * (Qq / QT), THREADS, SMEM_BYTES>>>(inputs, query);
    pool_kernel<<<Bb, 256>>>(inputs, out);
}